// round 3
// baseline (speedup 1.0000x reference)
#include <cuda_runtime.h>
#include <math.h>

#define NNODES 100000
#define NEDGES 1600000
#define NEG_SLOPE 0.2f
#define BN_EPS_C 1e-5f

// ----------------------------- scratch (device globals; allocation-free) ----
__device__ float g_tmpH[NNODES * 64];   // pre-aggregation features h = x@W
__device__ float g_h0[NNODES * 64];     // layer0 output (post elu)
__device__ float g_h1[NNODES * 64];     // layer1 output (post elu)
__device__ float g_tmpS[NNODES * 16];   // layer2 pre-aggregation features
__device__ float g_as[NNODES];          // alpha_src per node
__device__ float g_ad[NNODES];          // alpha_dst per node
__device__ int   g_deg1[NNODES], g_off1[NNODES];
__device__ int   g_deg2[NNODES], g_off2[NNODES];
__device__ int   g_cursor[NNODES];
__device__ int   g_srcs1[NEDGES], g_srcs2[NEDGES];
__device__ int   g_bsum[128];
__device__ float g_bnsum[16], g_bnsumsq[16];

__device__ __forceinline__ float lrelu(float x) { return x > 0.f ? x : NEG_SLOPE * x; }
__device__ __forceinline__ float elu1(float x)  { return x > 0.f ? x : expm1f(x); }

// ----------------------------- init ----------------------------------------
__global__ void zero_init_kernel() {
    int i = blockIdx.x * blockDim.x + threadIdx.x;
    if (i < NNODES) { g_deg1[i] = 0; g_deg2[i] = 0; }
    if (i < 16) { g_bnsum[i] = 0.f; g_bnsumsq[i] = 0.f; }
}

// ----------------------------- CSR build ------------------------------------
__global__ void count_deg_kernel(const int* __restrict__ ei, int* __restrict__ deg) {
    int e = blockIdx.x * blockDim.x + threadIdx.x;
    if (e < NEDGES) atomicAdd(&deg[ei[NEDGES + e]], 1);
}

// per-block inclusive scan -> exclusive offsets + block sums
__global__ void scan_blocks_kernel(const int* __restrict__ deg, int* __restrict__ off,
                                   int* __restrict__ bsum) {
    __shared__ int s[1024];
    int tid = threadIdx.x;
    int i = blockIdx.x * 1024 + tid;
    int v = (i < NNODES) ? deg[i] : 0;
    s[tid] = v;
    __syncthreads();
    for (int d = 1; d < 1024; d <<= 1) {
        int t = (tid >= d) ? s[tid - d] : 0;
        __syncthreads();
        if (tid >= d) s[tid] += t;
        __syncthreads();
    }
    if (i < NNODES) off[i] = s[tid] - v;  // exclusive
    if (tid == 1023) bsum[blockIdx.x] = s[1023];
}

__global__ void scan_partials_kernel(int* bsum, int nb) {
    int run = 0;
    for (int b = 0; b < nb; b++) { int t = bsum[b]; bsum[b] = run; run += t; }
}

__global__ void scan_add_kernel(int* __restrict__ off, const int* __restrict__ bsum,
                                int* __restrict__ cursor) {
    int i = blockIdx.x * 1024 + threadIdx.x;
    if (i < NNODES) {
        int o = off[i] + bsum[blockIdx.x];
        off[i] = o;
        cursor[i] = o;
    }
}

__global__ void scatter_kernel(const int* __restrict__ ei, int* __restrict__ cursor,
                               int* __restrict__ srcs) {
    int e = blockIdx.x * blockDim.x + threadIdx.x;
    if (e >= NEDGES) return;
    int src = ei[e];
    int dst = ei[NEDGES + e];
    int pos = atomicAdd(&cursor[dst], 1);
    srcs[pos] = src;
}

// ----------------------------- GEMM: C[N,BN] = [A1|A2] @ W ------------------
// W staged in SMEM, 4x4 register tile per thread, A loaded via broadcast LDG.
template <int BN, bool TWO>
__global__ void __launch_bounds__((BN / 4) * 16) gemm_kernel(
    const float* __restrict__ A1, const float* __restrict__ A2,
    const float* __restrict__ W, float* __restrict__ C) {
    constexpr int K = TWO ? 128 : 64;
    constexpr int NCOLT = BN / 4;              // thread cols
    constexpr int THREADS = NCOLT * 16;        // 16 thread-rows, 4 rows each
    constexpr int BM = 64;                     // rows per block
    __shared__ float Ws[K * BN];

    int tid = threadIdx.x;
    for (int idx = tid; idx < K * BN; idx += THREADS) Ws[idx] = W[idx];
    __syncthreads();

    int tcol = tid % NCOLT;
    int trow = tid / NCOLT;                    // 0..15
    int n0 = tcol * 4;
    int r0 = blockIdx.x * BM + trow * 4;

    float acc[4][4] = {};
    bool val[4];
    #pragma unroll
    for (int i = 0; i < 4; i++) val[i] = (r0 + i) < NNODES;

    #pragma unroll
    for (int seg = 0; seg < (TWO ? 2 : 1); seg++) {
        const float* A = (seg == 0) ? A1 : A2;
        #pragma unroll 4
        for (int kk = 0; kk < 64; kk++) {
            float4 wv = *reinterpret_cast<const float4*>(&Ws[(seg * 64 + kk) * BN + n0]);
            float a[4];
            #pragma unroll
            for (int i = 0; i < 4; i++)
                a[i] = val[i] ? __ldg(&A[(size_t)(r0 + i) * 64 + kk]) : 0.f;
            #pragma unroll
            for (int i = 0; i < 4; i++) {
                acc[i][0] += a[i] * wv.x;
                acc[i][1] += a[i] * wv.y;
                acc[i][2] += a[i] * wv.z;
                acc[i][3] += a[i] * wv.w;
            }
        }
    }
    #pragma unroll
    for (int i = 0; i < 4; i++) {
        if (val[i]) {
            float4 v = make_float4(acc[i][0], acc[i][1], acc[i][2], acc[i][3]);
            *reinterpret_cast<float4*>(&C[(size_t)(r0 + i) * BN + n0]) = v;
        }
    }
}

// ----------------------------- per-node attention dots ----------------------
template <int FOUT>
__global__ void node_dots_kernel(const float* __restrict__ h,
                                 const float* __restrict__ asrc,
                                 const float* __restrict__ adst,
                                 float* __restrict__ asv, float* __restrict__ adv) {
    int warp = (blockIdx.x * blockDim.x + threadIdx.x) >> 5;
    int lane = threadIdx.x & 31;
    if (warp >= NNODES) return;
    float s = 0.f, d = 0.f;
    if (FOUT == 64) {
        float v0 = h[(size_t)warp * 64 + lane];
        float v1 = h[(size_t)warp * 64 + 32 + lane];
        s = v0 * asrc[lane] + v1 * asrc[32 + lane];
        d = v0 * adst[lane] + v1 * adst[32 + lane];
    } else {
        if (lane < FOUT) {
            float v = h[(size_t)warp * FOUT + lane];
            s = v * asrc[lane];
            d = v * adst[lane];
        }
    }
    #pragma unroll
    for (int o = 16; o > 0; o >>= 1) {
        s += __shfl_xor_sync(0xffffffffu, s, o);
        d += __shfl_xor_sync(0xffffffffu, d, o);
    }
    if (lane == 0) { asv[warp] = s; adv[warp] = d; }
}

// ----------------------------- GAT aggregation (warp per node) --------------
template <int FOUT, bool DO_ELU>
__global__ void __launch_bounds__(256) aggregate_kernel(
    const float* __restrict__ h, const float* __restrict__ asv,
    const float* __restrict__ adv, const int* __restrict__ off,
    const int* __restrict__ deg, const int* __restrict__ srcs,
    const float* __restrict__ bias, float* __restrict__ out) {
    int warp = (blockIdx.x * blockDim.x + threadIdx.x) >> 5;
    int lane = threadIdx.x & 31;
    if (warp >= NNODES) return;
    const int i = warp;
    const float ad_i = adv[i];
    const float e_self = lrelu(asv[i] + ad_i);
    const int base = off[i];
    const int d = deg[i];

    // pass 1: segment max (self loop included)
    float m = e_self;
    for (int k = lane; k < d; k += 32) {
        int j = __ldg(&srcs[base + k]);
        m = fmaxf(m, lrelu(__ldg(&asv[j]) + ad_i));
    }
    #pragma unroll
    for (int s = 16; s > 0; s >>= 1) m = fmaxf(m, __shfl_xor_sync(0xffffffffu, m, s));

    // pass 2: exp-sum + weighted feature accumulation
    float w = expf(e_self - m);
    float denom = w;
    float acc0 = 0.f, acc1 = 0.f;
    if (FOUT == 64) {
        acc0 = w * h[(size_t)i * 64 + lane];
        acc1 = w * h[(size_t)i * 64 + 32 + lane];
    } else if (lane < FOUT) {
        acc0 = w * h[(size_t)i * FOUT + lane];
    }
    for (int k = 0; k < d; k++) {
        int j = __ldg(&srcs[base + k]);
        float wk = expf(lrelu(__ldg(&asv[j]) + ad_i) - m);
        denom += wk;
        if (FOUT == 64) {
            acc0 += wk * h[(size_t)j * 64 + lane];
            acc1 += wk * h[(size_t)j * 64 + 32 + lane];
        } else if (lane < FOUT) {
            acc0 += wk * h[(size_t)j * FOUT + lane];
        }
    }
    float inv = 1.0f / (denom + 1e-16f);
    if (FOUT == 64) {
        float v0 = acc0 * inv + bias[lane];
        float v1 = acc1 * inv + bias[lane + 32];
        out[(size_t)i * 64 + lane]      = DO_ELU ? elu1(v0) : v0;
        out[(size_t)i * 64 + 32 + lane] = DO_ELU ? elu1(v1) : v1;
    } else if (lane < FOUT) {
        float v0 = acc0 * inv + bias[lane];
        out[(size_t)i * FOUT + lane] = DO_ELU ? elu1(v0) : v0;
    }
}

// ----------------------------- BatchNorm stats ------------------------------
__global__ void bn_stats_kernel(const float* __restrict__ logits) {
    __shared__ float sh[16], sh2[16];
    if (threadIdx.x < 16) { sh[threadIdx.x] = 0.f; sh2[threadIdx.x] = 0.f; }
    __syncthreads();
    int c = threadIdx.x % 16;
    int group = (blockIdx.x * blockDim.x + threadIdx.x) / 16;
    int stride = (gridDim.x * blockDim.x) / 16;
    float s = 0.f, s2 = 0.f;
    for (int i = group; i < NNODES; i += stride) {
        float v = logits[(size_t)i * 16 + c];
        s += v;
        s2 += v * v;
    }
    atomicAdd(&sh[c], s);
    atomicAdd(&sh2[c], s2);
    __syncthreads();
    if (threadIdx.x < 16) {
        atomicAdd(&g_bnsum[threadIdx.x], sh[threadIdx.x]);
        atomicAdd(&g_bnsumsq[threadIdx.x], sh2[threadIdx.x]);
    }
}

// ----------------------------- BN + log_softmax (in place) ------------------
__global__ void bn_lsm_kernel(float* __restrict__ out, const float* __restrict__ gamma,
                              const float* __restrict__ beta) {
    int i = blockIdx.x * blockDim.x + threadIdx.x;
    if (i >= NNODES) return;
    float y[16];
    float maxv = -1e30f;
    const float invN = 1.0f / (float)NNODES;
    #pragma unroll
    for (int c = 0; c < 16; c++) {
        float mu = g_bnsum[c] * invN;
        float var = g_bnsumsq[c] * invN - mu * mu;
        float v = out[(size_t)i * 16 + c];
        float yy = (v - mu) * rsqrtf(var + BN_EPS_C) * gamma[c] + beta[c];
        y[c] = yy;
        maxv = fmaxf(maxv, yy);
    }
    float s = 0.f;
    #pragma unroll
    for (int c = 0; c < 16; c++) s += expf(y[c] - maxv);
    float lse = maxv + logf(s);
    #pragma unroll
    for (int c = 0; c < 16; c++) out[(size_t)i * 16 + c] = y[c] - lse;
}

// ----------------------------- driver ---------------------------------------
extern "C" void kernel_launch(void* const* d_in, const int* in_sizes, int n_in,
                              void* d_out, int out_size) {
    const float* x1    = (const float*)d_in[0];
    const float* x2    = (const float*)d_in[1];
    const int*   ei1   = (const int*)d_in[2];
    const int*   ei2   = (const int*)d_in[3];
    const float* W0    = (const float*)d_in[4];
    const float* asrc0 = (const float*)d_in[5];
    const float* adst0 = (const float*)d_in[6];
    const float* b0    = (const float*)d_in[7];
    const float* W1    = (const float*)d_in[8];
    const float* asrc1 = (const float*)d_in[9];
    const float* adst1 = (const float*)d_in[10];
    const float* b1    = (const float*)d_in[11];
    const float* W2    = (const float*)d_in[12];
    const float* asrc2 = (const float*)d_in[13];
    const float* adst2 = (const float*)d_in[14];
    const float* b2    = (const float*)d_in[15];
    const float* gamma = (const float*)d_in[16];
    const float* beta  = (const float*)d_in[17];
    float* out = (float*)d_out;

    float *tmpH, *h0, *h1, *tmpS, *asv, *adv;
    int *deg1, *off1, *deg2, *off2, *cursor, *srcs1, *srcs2, *bsum;
    cudaGetSymbolAddress((void**)&tmpH, g_tmpH);
    cudaGetSymbolAddress((void**)&h0, g_h0);
    cudaGetSymbolAddress((void**)&h1, g_h1);
    cudaGetSymbolAddress((void**)&tmpS, g_tmpS);
    cudaGetSymbolAddress((void**)&asv, g_as);
    cudaGetSymbolAddress((void**)&adv, g_ad);
    cudaGetSymbolAddress((void**)&deg1, g_deg1);
    cudaGetSymbolAddress((void**)&off1, g_off1);
    cudaGetSymbolAddress((void**)&deg2, g_deg2);
    cudaGetSymbolAddress((void**)&off2, g_off2);
    cudaGetSymbolAddress((void**)&cursor, g_cursor);
    cudaGetSymbolAddress((void**)&srcs1, g_srcs1);
    cudaGetSymbolAddress((void**)&srcs2, g_srcs2);
    cudaGetSymbolAddress((void**)&bsum, g_bsum);

    const int EB = (NEDGES + 255) / 256;
    const int NB = (NNODES + 1023) / 1024;
    const int WARP_BLOCKS = (NNODES + 7) / 8;  // warp-per-node, 256 thr

    zero_init_kernel<<<(NNODES + 255) / 256, 256>>>();

    // CSR for graph 1
    count_deg_kernel<<<EB, 256>>>(ei1, deg1);
    scan_blocks_kernel<<<NB, 1024>>>(deg1, off1, bsum);
    scan_partials_kernel<<<1, 1>>>(bsum, NB);
    scan_add_kernel<<<NB, 1024>>>(off1, bsum, cursor);
    scatter_kernel<<<EB, 256>>>(ei1, cursor, srcs1);
    // CSR for graph 2
    count_deg_kernel<<<EB, 256>>>(ei2, deg2);
    scan_blocks_kernel<<<NB, 1024>>>(deg2, off2, bsum);
    scan_partials_kernel<<<1, 1>>>(bsum, NB);
    scan_add_kernel<<<NB, 1024>>>(off2, bsum, cursor);
    scatter_kernel<<<EB, 256>>>(ei2, cursor, srcs2);

    // ---- layer 0: h0 = elu(GAT(x1, graph1; W0)) ----
    gemm_kernel<64, false><<<(NNODES + 63) / 64, 256>>>(x1, nullptr, W0, tmpH);
    node_dots_kernel<64><<<WARP_BLOCKS, 256>>>(tmpH, asrc0, adst0, asv, adv);
    aggregate_kernel<64, true><<<WARP_BLOCKS, 256>>>(tmpH, asv, adv, off1, deg1, srcs1, b0, h0);

    // ---- layer 1: h1 = elu(GAT(concat(h0,x2), graph2; W1)) ----
    gemm_kernel<64, true><<<(NNODES + 63) / 64, 256>>>(h0, x2, W1, tmpH);
    node_dots_kernel<64><<<WARP_BLOCKS, 256>>>(tmpH, asrc1, adst1, asv, adv);
    aggregate_kernel<64, true><<<WARP_BLOCKS, 256>>>(tmpH, asv, adv, off2, deg2, srcs2, b1, h1);

    // ---- layer 2: logits = GAT(concat(h0,h1), graph2; W2) -> d_out ----
    gemm_kernel<16, true><<<(NNODES + 63) / 64, 64>>>(h0, h1, W2, tmpS);
    node_dots_kernel<16><<<WARP_BLOCKS, 256>>>(tmpS, asrc2, adst2, asv, adv);
    aggregate_kernel<16, false><<<WARP_BLOCKS, 256>>>(tmpS, asv, adv, off2, deg2, srcs2, b2, out);

    // ---- BatchNorm + log_softmax ----
    bn_stats_kernel<<<256, 256>>>(out);
    bn_lsm_kernel<<<(NNODES + 255) / 256, 256>>>(out, gamma, beta);
}

// round 4
// speedup vs baseline: 1.8036x; 1.8036x over previous
#include <cuda_runtime.h>
#include <math.h>

#define NNODES 100000
#define NEDGES 1600000
#define NEG_SLOPE 0.2f
#define BN_EPS_C 1e-5f
#define NB_SCAN 98   // ceil(100000/1024)

// ----------------------------- scratch (device globals; allocation-free) ----
__device__ float g_tmpH[NNODES * 64];
__device__ float g_h0[NNODES * 64];
__device__ float g_h1[NNODES * 64];
__device__ float g_tmpS[NNODES * 16];
__device__ float g_as[NNODES];
__device__ float g_ad[NNODES];
__device__ int   g_deg1[NNODES], g_off1[NNODES];
__device__ int   g_deg2[NNODES], g_off2[NNODES];
__device__ int   g_cursor1[NNODES], g_cursor2[NNODES];
__device__ int   g_srcs1[NEDGES], g_srcs2[NEDGES];
__device__ int   g_bsum[256];
__device__ float g_bnsum[16], g_bnsumsq[16];

__device__ __forceinline__ float lrelu(float x) { return x > 0.f ? x : NEG_SLOPE * x; }
__device__ __forceinline__ float elu1(float x)  { return x > 0.f ? x : expm1f(x); }

// ----------------------------- init ----------------------------------------
__global__ void zero_init_kernel() {
    int i = blockIdx.x * blockDim.x + threadIdx.x;
    if (i < NNODES) { g_deg1[i] = 0; g_deg2[i] = 0; }
    if (i < 16) { g_bnsum[i] = 0.f; g_bnsumsq[i] = 0.f; }
}

// ----------------------------- CSR build (both graphs in one launch) --------
__global__ void count_deg2_kernel(const int* __restrict__ ei1, const int* __restrict__ ei2) {
    int e = blockIdx.x * blockDim.x + threadIdx.x;
    if (e < NEDGES)           atomicAdd(&g_deg1[ei1[NEDGES + e]], 1);
    else if (e < 2 * NEDGES)  atomicAdd(&g_deg2[ei2[e]], 1);  // e-NEDGES+NEDGES = e
}

__global__ void scan_blocks2_kernel() {
    __shared__ int s[1024];
    int tid = threadIdx.x;
    int graph = (blockIdx.x >= NB_SCAN);
    int lb = blockIdx.x - graph * NB_SCAN;
    const int* deg = graph ? g_deg2 : g_deg1;
    int* off = graph ? g_off2 : g_off1;
    int i = lb * 1024 + tid;
    int v = (i < NNODES) ? deg[i] : 0;
    s[tid] = v;
    __syncthreads();
    for (int d = 1; d < 1024; d <<= 1) {
        int t = (tid >= d) ? s[tid - d] : 0;
        __syncthreads();
        if (tid >= d) s[tid] += t;
        __syncthreads();
    }
    if (i < NNODES) off[i] = s[tid] - v;  // exclusive
    if (tid == 1023) g_bsum[graph * NB_SCAN + lb] = s[1023];
}

// one block, 256 threads: parallel exclusive scan of the 2*98 block sums
__global__ void scan_partials2_kernel() {
    __shared__ int s[256];
    int tid = threadIdx.x;
    int half = tid >> 7;        // 0 or 1
    int idx = tid & 127;
    int v = (idx < NB_SCAN) ? g_bsum[half * NB_SCAN + idx] : 0;
    s[tid] = v;
    __syncthreads();
    for (int d = 1; d < 128; d <<= 1) {
        int t = (idx >= d) ? s[tid - d] : 0;
        __syncthreads();
        s[tid] += t;
        __syncthreads();
    }
    if (idx < NB_SCAN) g_bsum[half * NB_SCAN + idx] = s[tid] - v;  // exclusive
}

__global__ void scan_add2_kernel() {
    int graph = (blockIdx.x >= NB_SCAN);
    int lb = blockIdx.x - graph * NB_SCAN;
    int* off = graph ? g_off2 : g_off1;
    int* cur = graph ? g_cursor2 : g_cursor1;
    int i = lb * 1024 + threadIdx.x;
    if (i < NNODES) {
        int o = off[i] + g_bsum[graph * NB_SCAN + lb];
        off[i] = o;
        cur[i] = o;
    }
}

__global__ void scatter2_kernel(const int* __restrict__ ei1, const int* __restrict__ ei2) {
    int e = blockIdx.x * blockDim.x + threadIdx.x;
    if (e < NEDGES) {
        int src = ei1[e];
        int dst = ei1[NEDGES + e];
        int pos = atomicAdd(&g_cursor1[dst], 1);
        g_srcs1[pos] = src;
    } else if (e < 2 * NEDGES) {
        int e2 = e - NEDGES;
        int src = ei2[e2];
        int dst = ei2[e2 + NEDGES];
        int pos = atomicAdd(&g_cursor2[dst], 1);
        g_srcs2[pos] = src;
    }
}

// ----------------------------- GEMM + attention dots fused ------------------
// C[N,BN] = [A1|A2] @ W ; asv[i] = C[i,:]@a_src ; adv[i] = C[i,:]@a_dst
template <int BN, bool TWO>
__global__ void __launch_bounds__((BN / 4) * 16) gemm_dots_kernel(
    const float* __restrict__ A1, const float* __restrict__ A2,
    const float* __restrict__ W,
    const float* __restrict__ a_src, const float* __restrict__ a_dst,
    float* __restrict__ C, float* __restrict__ asv, float* __restrict__ adv) {
    constexpr int K = TWO ? 128 : 64;
    constexpr int NCOLT = BN / 4;
    constexpr int THREADS = NCOLT * 16;
    constexpr int BM = 64;
    __shared__ float Ws[K * BN];

    int tid = threadIdx.x;
    for (int idx = tid; idx < K * BN; idx += THREADS) Ws[idx] = W[idx];
    __syncthreads();

    int tcol = tid % NCOLT;
    int trow = tid / NCOLT;
    int n0 = tcol * 4;
    int r0 = blockIdx.x * BM + trow * 4;

    float acc[4][4] = {};
    bool val[4];
    #pragma unroll
    for (int i = 0; i < 4; i++) val[i] = (r0 + i) < NNODES;

    #pragma unroll
    for (int seg = 0; seg < (TWO ? 2 : 1); seg++) {
        const float* A = (seg == 0) ? A1 : A2;
        #pragma unroll 4
        for (int kk = 0; kk < 64; kk++) {
            float4 wv = *reinterpret_cast<const float4*>(&Ws[(seg * 64 + kk) * BN + n0]);
            float a[4];
            #pragma unroll
            for (int i = 0; i < 4; i++)
                a[i] = val[i] ? __ldg(&A[(size_t)(r0 + i) * 64 + kk]) : 0.f;
            #pragma unroll
            for (int i = 0; i < 4; i++) {
                acc[i][0] += a[i] * wv.x;
                acc[i][1] += a[i] * wv.y;
                acc[i][2] += a[i] * wv.z;
                acc[i][3] += a[i] * wv.w;
            }
        }
    }
    #pragma unroll
    for (int i = 0; i < 4; i++) {
        if (val[i]) {
            float4 v = make_float4(acc[i][0], acc[i][1], acc[i][2], acc[i][3]);
            *reinterpret_cast<float4*>(&C[(size_t)(r0 + i) * BN + n0]) = v;
        }
    }
    // ---- fused attention dot epilogue ----
    float4 asv4 = *reinterpret_cast<const float4*>(&a_src[n0]);
    float4 adv4 = *reinterpret_cast<const float4*>(&a_dst[n0]);
    float s_par[4], d_par[4];
    #pragma unroll
    for (int i = 0; i < 4; i++) {
        s_par[i] = acc[i][0] * asv4.x + acc[i][1] * asv4.y + acc[i][2] * asv4.z + acc[i][3] * asv4.w;
        d_par[i] = acc[i][0] * adv4.x + acc[i][1] * adv4.y + acc[i][2] * adv4.z + acc[i][3] * adv4.w;
    }
    #pragma unroll
    for (int o = NCOLT / 2; o > 0; o >>= 1) {
        #pragma unroll
        for (int i = 0; i < 4; i++) {
            s_par[i] += __shfl_xor_sync(0xffffffffu, s_par[i], o);
            d_par[i] += __shfl_xor_sync(0xffffffffu, d_par[i], o);
        }
    }
    if (tcol == 0) {
        #pragma unroll
        for (int i = 0; i < 4; i++) {
            if (val[i]) { asv[r0 + i] = s_par[i]; adv[r0 + i] = d_par[i]; }
        }
    }
}

// ----------------------------- GAT aggregation, F=64 (warp per node) --------
// Unnormalized softmax (no max pass; e is bounded by a few units, exp safe).
// Per 32-edge chunk: lane-parallel weight computation, then 4x-unrolled
// shfl-broadcast accumulation (8 independent h loads in flight).
template <bool DO_ELU>
__global__ void __launch_bounds__(256) agg64_kernel(
    const float* __restrict__ h, const float* __restrict__ asv,
    const float* __restrict__ adv, const int* __restrict__ off,
    const int* __restrict__ deg, const int* __restrict__ srcs,
    const float* __restrict__ bias, float* __restrict__ out) {
    const int i = (blockIdx.x * blockDim.x + threadIdx.x) >> 5;  // exact: 12500*8 = 100000
    const int lane = threadIdx.x & 31;
    const float ad_i = __ldg(&adv[i]);
    const int base = __ldg(&off[i]);
    const int d = __ldg(&deg[i]);

    float wself = __expf(lrelu(__ldg(&asv[i]) + ad_i));
    float denom = wself;
    float acc0 = wself * h[(size_t)i * 64 + lane];
    float acc1 = wself * h[(size_t)i * 64 + 32 + lane];

    for (int k0 = 0; k0 < d; k0 += 32) {
        int kk = k0 + lane;
        int j = 0; float wv = 0.f;
        if (kk < d) {
            j = __ldg(&srcs[base + kk]);
            wv = __expf(lrelu(__ldg(&asv[j]) + ad_i));
        }
        float ws = wv;
        #pragma unroll
        for (int o = 16; o > 0; o >>= 1) ws += __shfl_xor_sync(0xffffffffu, ws, o);
        denom += ws;

        int cnt = min(32, d - k0);
        int k = 0;
        for (; k + 4 <= cnt; k += 4) {
            int j0 = __shfl_sync(0xffffffffu, j, k);
            int j1 = __shfl_sync(0xffffffffu, j, k + 1);
            int j2 = __shfl_sync(0xffffffffu, j, k + 2);
            int j3 = __shfl_sync(0xffffffffu, j, k + 3);
            float w0 = __shfl_sync(0xffffffffu, wv, k);
            float w1 = __shfl_sync(0xffffffffu, wv, k + 1);
            float w2 = __shfl_sync(0xffffffffu, wv, k + 2);
            float w3 = __shfl_sync(0xffffffffu, wv, k + 3);
            float h00 = h[(size_t)j0 * 64 + lane], h01 = h[(size_t)j0 * 64 + 32 + lane];
            float h10 = h[(size_t)j1 * 64 + lane], h11 = h[(size_t)j1 * 64 + 32 + lane];
            float h20 = h[(size_t)j2 * 64 + lane], h21 = h[(size_t)j2 * 64 + 32 + lane];
            float h30 = h[(size_t)j3 * 64 + lane], h31 = h[(size_t)j3 * 64 + 32 + lane];
            acc0 += w0 * h00; acc1 += w0 * h01;
            acc0 += w1 * h10; acc1 += w1 * h11;
            acc0 += w2 * h20; acc1 += w2 * h21;
            acc0 += w3 * h30; acc1 += w3 * h31;
        }
        for (; k < cnt; k++) {
            int jj = __shfl_sync(0xffffffffu, j, k);
            float wk = __shfl_sync(0xffffffffu, wv, k);
            acc0 += wk * h[(size_t)jj * 64 + lane];
            acc1 += wk * h[(size_t)jj * 64 + 32 + lane];
        }
    }
    float inv = 1.0f / (denom + 1e-16f);
    float v0 = acc0 * inv + __ldg(&bias[lane]);
    float v1 = acc1 * inv + __ldg(&bias[32 + lane]);
    out[(size_t)i * 64 + lane]      = DO_ELU ? elu1(v0) : v0;
    out[(size_t)i * 64 + 32 + lane] = DO_ELU ? elu1(v1) : v1;
}

// ----------------------------- GAT aggregation, F=16 + fused BN stats -------
// Half-warps process two edges per step (lane = e*16 + f).
__global__ void __launch_bounds__(256) agg16_bn_kernel(
    const float* __restrict__ h, const float* __restrict__ asv,
    const float* __restrict__ adv, const int* __restrict__ off,
    const int* __restrict__ deg, const int* __restrict__ srcs,
    const float* __restrict__ bias, float* __restrict__ out) {
    __shared__ float shs[16], shs2[16];
    if (threadIdx.x < 16) { shs[threadIdx.x] = 0.f; shs2[threadIdx.x] = 0.f; }
    __syncthreads();

    const int i = (blockIdx.x * blockDim.x + threadIdx.x) >> 5;
    const int lane = threadIdx.x & 31;
    const int e = lane >> 4;    // half-warp id
    const int f = lane & 15;    // feature id
    const float ad_i = __ldg(&adv[i]);
    const int base = __ldg(&off[i]);
    const int d = __ldg(&deg[i]);

    float wself = __expf(lrelu(__ldg(&asv[i]) + ad_i));
    float denom = wself;
    float acc = (e == 0) ? wself * h[(size_t)i * 16 + f] : 0.f;

    for (int k0 = 0; k0 < d; k0 += 32) {
        int kk = k0 + lane;
        int j = 0; float wv = 0.f;
        if (kk < d) {
            j = __ldg(&srcs[base + kk]);
            wv = __expf(lrelu(__ldg(&asv[j]) + ad_i));
        }
        float ws = wv;
        #pragma unroll
        for (int o = 16; o > 0; o >>= 1) ws += __shfl_xor_sync(0xffffffffu, ws, o);
        denom += ws;

        int cnt = min(32, d - k0);
        int k = 0;
        for (; k + 4 <= cnt; k += 4) {
            int ja = __shfl_sync(0xffffffffu, j, k + e);
            int jb = __shfl_sync(0xffffffffu, j, k + 2 + e);
            float wa = __shfl_sync(0xffffffffu, wv, k + e);
            float wb = __shfl_sync(0xffffffffu, wv, k + 2 + e);
            float ha = h[(size_t)ja * 16 + f];
            float hb = h[(size_t)jb * 16 + f];
            acc += wa * ha + wb * hb;
        }
        for (; k < cnt; k += 2) {
            int km = min(k + e, 31);
            int ja = __shfl_sync(0xffffffffu, j, km);
            float wa = __shfl_sync(0xffffffffu, wv, km);
            if (k + e < cnt) acc += wa * h[(size_t)ja * 16 + f];
        }
    }
    acc += __shfl_xor_sync(0xffffffffu, acc, 16);  // combine half-warps
    float inv = 1.0f / (denom + 1e-16f);
    if (e == 0) {
        float v = acc * inv + __ldg(&bias[f]);
        out[(size_t)i * 16 + f] = v;
        atomicAdd(&shs[f], v);
        atomicAdd(&shs2[f], v * v);
    }
    __syncthreads();
    if (threadIdx.x < 16) {
        atomicAdd(&g_bnsum[threadIdx.x], shs[threadIdx.x]);
        atomicAdd(&g_bnsumsq[threadIdx.x], shs2[threadIdx.x]);
    }
}

// ----------------------------- BN + log_softmax (in place) ------------------
__global__ void bn_lsm_kernel(float* __restrict__ out, const float* __restrict__ gamma,
                              const float* __restrict__ beta) {
    int i = blockIdx.x * blockDim.x + threadIdx.x;
    if (i >= NNODES) return;
    float y[16];
    float maxv = -1e30f;
    const float invN = 1.0f / (float)NNODES;
    #pragma unroll
    for (int c = 0; c < 16; c++) {
        float mu = g_bnsum[c] * invN;
        float var = g_bnsumsq[c] * invN - mu * mu;
        float v = out[(size_t)i * 16 + c];
        float yy = (v - mu) * rsqrtf(var + BN_EPS_C) * gamma[c] + beta[c];
        y[c] = yy;
        maxv = fmaxf(maxv, yy);
    }
    float s = 0.f;
    #pragma unroll
    for (int c = 0; c < 16; c++) s += expf(y[c] - maxv);
    float lse = maxv + logf(s);
    #pragma unroll
    for (int c = 0; c < 16; c++) out[(size_t)i * 16 + c] = y[c] - lse;
}

// ----------------------------- driver ---------------------------------------
extern "C" void kernel_launch(void* const* d_in, const int* in_sizes, int n_in,
                              void* d_out, int out_size) {
    const float* x1    = (const float*)d_in[0];
    const float* x2    = (const float*)d_in[1];
    const int*   ei1   = (const int*)d_in[2];
    const int*   ei2   = (const int*)d_in[3];
    const float* W0    = (const float*)d_in[4];
    const float* asrc0 = (const float*)d_in[5];
    const float* adst0 = (const float*)d_in[6];
    const float* b0    = (const float*)d_in[7];
    const float* W1    = (const float*)d_in[8];
    const float* asrc1 = (const float*)d_in[9];
    const float* adst1 = (const float*)d_in[10];
    const float* b1    = (const float*)d_in[11];
    const float* W2    = (const float*)d_in[12];
    const float* asrc2 = (const float*)d_in[13];
    const float* adst2 = (const float*)d_in[14];
    const float* b2    = (const float*)d_in[15];
    const float* gamma = (const float*)d_in[16];
    const float* beta  = (const float*)d_in[17];
    float* out = (float*)d_out;

    float *tmpH, *h0, *h1, *tmpS, *asv, *adv;
    int *deg1, *off1, *deg2, *off2, *srcs1, *srcs2;
    cudaGetSymbolAddress((void**)&tmpH, g_tmpH);
    cudaGetSymbolAddress((void**)&h0, g_h0);
    cudaGetSymbolAddress((void**)&h1, g_h1);
    cudaGetSymbolAddress((void**)&tmpS, g_tmpS);
    cudaGetSymbolAddress((void**)&asv, g_as);
    cudaGetSymbolAddress((void**)&adv, g_ad);
    cudaGetSymbolAddress((void**)&deg1, g_deg1);
    cudaGetSymbolAddress((void**)&off1, g_off1);
    cudaGetSymbolAddress((void**)&deg2, g_deg2);
    cudaGetSymbolAddress((void**)&off2, g_off2);
    cudaGetSymbolAddress((void**)&srcs1, g_srcs1);
    cudaGetSymbolAddress((void**)&srcs2, g_srcs2);

    const int EB2 = (2 * NEDGES + 255) / 256;
    const int WARP_BLOCKS = NNODES / 8;        // exact: 12500 blocks * 8 warps

    zero_init_kernel<<<(NNODES + 255) / 256, 256>>>();                   // 0

    // CSR for both graphs (fused launches)
    count_deg2_kernel<<<EB2, 256>>>(ei1, ei2);                           // 1
    scan_blocks2_kernel<<<2 * NB_SCAN, 1024>>>();                        // 2
    scan_partials2_kernel<<<1, 256>>>();                                 // 3
    scan_add2_kernel<<<2 * NB_SCAN, 1024>>>();                           // 4
    scatter2_kernel<<<EB2, 256>>>(ei1, ei2);                             // 5 (profiled)

    // ---- layer 0: h0 = elu(GAT(x1, graph1; W0)) ----
    gemm_dots_kernel<64, false><<<(NNODES + 63) / 64, 256>>>(
        x1, nullptr, W0, asrc0, adst0, tmpH, asv, adv);
    agg64_kernel<true><<<WARP_BLOCKS, 256>>>(tmpH, asv, adv, off1, deg1, srcs1, b0, h0);

    // ---- layer 1: h1 = elu(GAT(concat(h0,x2), graph2; W1)) ----
    gemm_dots_kernel<64, true><<<(NNODES + 63) / 64, 256>>>(
        h0, x2, W1, asrc1, adst1, tmpH, asv, adv);
    agg64_kernel<true><<<WARP_BLOCKS, 256>>>(tmpH, asv, adv, off2, deg2, srcs2, b1, h1);

    // ---- layer 2: logits = GAT(concat(h0,h1), graph2; W2) -> d_out, + BN stats ----
    gemm_dots_kernel<16, true><<<(NNODES + 63) / 64, 64>>>(
        h0, h1, W2, asrc2, adst2, tmpS, asv, adv);
    agg16_bn_kernel<<<WARP_BLOCKS, 256>>>(tmpS, asv, adv, off2, deg2, srcs2, b2, out);

    // ---- BN + log_softmax ----
    bn_lsm_kernel<<<(NNODES + 255) / 256, 256>>>(out, gamma, beta);
}

// round 5
// speedup vs baseline: 2.1978x; 1.2186x over previous
#include <cuda_runtime.h>
#include <math.h>

#define NNODES 100000
#define NEDGES 1600000
#define NEG_SLOPE 0.2f
#define BN_EPS_C 1e-5f
#define EB 6250        // NEDGES / 256
#define NB98 98        // ceil(NNODES / 1024)
#define GB64 1563      // ceil(NNODES / 64)
#define GB256 391      // ceil(NNODES / 256)
#define WARPB 12500    // NNODES / 8 warps-per-node blocks

// ----------------------------- scratch (device globals; allocation-free) ----
__device__ float g_tmpH[NNODES * 64];
__device__ float g_h0[NNODES * 64];
__device__ float g_h1[NNODES * 64];
__device__ float g_tmpS[NNODES * 16];
__device__ float g_as[NNODES];
__device__ float g_ad[NNODES];
__device__ int   g_deg1[NNODES], g_off1[NNODES];
__device__ int   g_deg2[NNODES], g_off2[NNODES];
__device__ int   g_cursor1[NNODES], g_cursor2[NNODES];
__device__ int   g_srcs1[NEDGES], g_srcs2[NEDGES];
__device__ int   g_bsum1[NB98], g_bsum2[NB98];
__device__ float g_bnsum[16], g_bnsumsq[16];

__device__ __forceinline__ float lrelu(float x) { return x > 0.f ? x : NEG_SLOPE * x; }
__device__ __forceinline__ float elu1(float x)  { return x > 0.f ? x : expm1f(x); }

// ============================ device building blocks ========================

__device__ __forceinline__ void dev_count(const int* __restrict__ ei,
                                          int* __restrict__ deg, int bid) {
    int e = bid * 256 + threadIdx.x;
    if (e < NEDGES) atomicAdd(&deg[__ldg(&ei[NEDGES + e])], 1);
}

__device__ __forceinline__ void dev_scatter(const int* __restrict__ ei,
                                            int* __restrict__ cursor,
                                            int* __restrict__ srcs, int bid) {
    int e = bid * 256 + threadIdx.x;
    if (e < NEDGES) {
        int src = __ldg(&ei[e]);
        int dst = __ldg(&ei[NEDGES + e]);
        srcs[atomicAdd(&cursor[dst], 1)] = src;
    }
}

// 256 threads, 1024 elements per block: local exclusive scan + block sum
__device__ void dev_scanb(const int* __restrict__ deg, int* __restrict__ off,
                          int* __restrict__ bsum, int lb) {
    __shared__ int sh[256];
    int tid = threadIdx.x;
    int base = lb * 1024 + tid * 4;
    int4 v = make_int4(0, 0, 0, 0);
    if (base + 3 < NNODES) {
        v = *reinterpret_cast<const int4*>(&deg[base]);
    } else {
        if (base + 0 < NNODES) v.x = deg[base + 0];
        if (base + 1 < NNODES) v.y = deg[base + 1];
        if (base + 2 < NNODES) v.z = deg[base + 2];
        if (base + 3 < NNODES) v.w = deg[base + 3];
    }
    int lsum = v.x + v.y + v.z + v.w;
    sh[tid] = lsum;
    __syncthreads();
    for (int d = 1; d < 256; d <<= 1) {
        int t = (tid >= d) ? sh[tid - d] : 0;
        __syncthreads();
        if (tid >= d) sh[tid] += t;
        __syncthreads();
    }
    int ex = sh[tid] - lsum;   // exclusive prefix within block
    int e0 = ex, e1 = ex + v.x, e2 = e1 + v.y, e3 = e2 + v.z;
    if (base + 3 < NNODES) {
        *reinterpret_cast<int4*>(&off[base]) = make_int4(e0, e1, e2, e3);
    } else {
        if (base + 0 < NNODES) off[base + 0] = e0;
        if (base + 1 < NNODES) off[base + 1] = e1;
        if (base + 2 < NNODES) off[base + 2] = e2;
        if (base + 3 < NNODES) off[base + 3] = e3;
    }
    if (tid == 255) bsum[lb] = sh[255];
}

// 1 block, 256 threads: exclusive scan of 98 block sums
__device__ void dev_scanp(int* __restrict__ bsum) {
    __shared__ int sh[256];
    int tid = threadIdx.x;
    int v = (tid < NB98) ? bsum[tid] : 0;
    sh[tid] = v;
    __syncthreads();
    for (int d = 1; d < 256; d <<= 1) {
        int t = (tid >= d) ? sh[tid - d] : 0;
        __syncthreads();
        if (tid >= d) sh[tid] += t;
        __syncthreads();
    }
    if (tid < NB98) bsum[tid] = sh[tid] - v;
}

__device__ void dev_scana(int* __restrict__ off, const int* __restrict__ bsum,
                          int* __restrict__ cursor, int lb) {
    int base = lb * 1024 + threadIdx.x * 4;
    int p = bsum[lb];
    if (base + 3 < NNODES) {
        int4 o = *reinterpret_cast<const int4*>(&off[base]);
        o.x += p; o.y += p; o.z += p; o.w += p;
        *reinterpret_cast<int4*>(&off[base]) = o;
        *reinterpret_cast<int4*>(&cursor[base]) = o;
    } else {
        #pragma unroll
        for (int t = 0; t < 4; t++) {
            if (base + t < NNODES) {
                int o = off[base + t] + p;
                off[base + t] = o;
                cursor[base + t] = o;
            }
        }
    }
}

// GEMM + attention-dot epilogue. 256 threads. BM = (256/(BN/4))*4 rows/block.
template <int BN, bool TWO>
__device__ void dev_gemm_dots(const float* __restrict__ A1, const float* __restrict__ A2,
                              const float* __restrict__ W,
                              const float* __restrict__ a_src, const float* __restrict__ a_dst,
                              float* __restrict__ C, float* __restrict__ asv,
                              float* __restrict__ adv, int bid) {
    constexpr int K = TWO ? 128 : 64;
    constexpr int NCOLT = BN / 4;
    constexpr int NROWT = 256 / NCOLT;
    constexpr int BM = NROWT * 4;
    __shared__ float Ws[K * BN];

    int tid = threadIdx.x;
    for (int idx = tid; idx < K * BN; idx += 256) Ws[idx] = W[idx];
    __syncthreads();

    int tcol = tid % NCOLT;
    int trow = tid / NCOLT;
    int n0 = tcol * 4;
    int r0 = bid * BM + trow * 4;

    float acc[4][4] = {};
    bool val[4];
    #pragma unroll
    for (int i = 0; i < 4; i++) val[i] = (r0 + i) < NNODES;

    #pragma unroll
    for (int seg = 0; seg < (TWO ? 2 : 1); seg++) {
        const float* A = (seg == 0) ? A1 : A2;
        #pragma unroll 4
        for (int k4 = 0; k4 < 16; k4++) {
            float a[4][4];
            #pragma unroll
            for (int i = 0; i < 4; i++) {
                float4 t = val[i]
                    ? *reinterpret_cast<const float4*>(&A[(size_t)(r0 + i) * 64 + k4 * 4])
                    : make_float4(0.f, 0.f, 0.f, 0.f);
                a[i][0] = t.x; a[i][1] = t.y; a[i][2] = t.z; a[i][3] = t.w;
            }
            #pragma unroll
            for (int s = 0; s < 4; s++) {
                float4 wv = *reinterpret_cast<const float4*>(
                    &Ws[(seg * 64 + k4 * 4 + s) * BN + n0]);
                #pragma unroll
                for (int i = 0; i < 4; i++) {
                    acc[i][0] += a[i][s] * wv.x;
                    acc[i][1] += a[i][s] * wv.y;
                    acc[i][2] += a[i][s] * wv.z;
                    acc[i][3] += a[i][s] * wv.w;
                }
            }
        }
    }
    #pragma unroll
    for (int i = 0; i < 4; i++) {
        if (val[i]) {
            *reinterpret_cast<float4*>(&C[(size_t)(r0 + i) * BN + n0]) =
                make_float4(acc[i][0], acc[i][1], acc[i][2], acc[i][3]);
        }
    }
    // fused attention dots
    float4 as4 = *reinterpret_cast<const float4*>(&a_src[n0]);
    float4 ad4 = *reinterpret_cast<const float4*>(&a_dst[n0]);
    float s_par[4], d_par[4];
    #pragma unroll
    for (int i = 0; i < 4; i++) {
        s_par[i] = acc[i][0] * as4.x + acc[i][1] * as4.y + acc[i][2] * as4.z + acc[i][3] * as4.w;
        d_par[i] = acc[i][0] * ad4.x + acc[i][1] * ad4.y + acc[i][2] * ad4.z + acc[i][3] * ad4.w;
    }
    #pragma unroll
    for (int o = NCOLT / 2; o > 0; o >>= 1) {
        #pragma unroll
        for (int i = 0; i < 4; i++) {
            s_par[i] += __shfl_xor_sync(0xffffffffu, s_par[i], o);
            d_par[i] += __shfl_xor_sync(0xffffffffu, d_par[i], o);
        }
    }
    if (tcol == 0) {
        #pragma unroll
        for (int i = 0; i < 4; i++) {
            if (val[i]) { asv[r0 + i] = s_par[i]; adv[r0 + i] = d_par[i]; }
        }
    }
}

// GAT aggregation F=64, warp per node, unnormalized softmax (e bounded).
template <bool DO_ELU>
__device__ void dev_agg64(const float* __restrict__ h, const float* __restrict__ asv,
                          const float* __restrict__ adv, const int* __restrict__ off,
                          const int* __restrict__ deg, const int* __restrict__ srcs,
                          const float* __restrict__ bias, float* __restrict__ out, int bid) {
    const int i = bid * 8 + (threadIdx.x >> 5);
    const int lane = threadIdx.x & 31;
    const float ad_i = __ldg(&adv[i]);
    const int base = __ldg(&off[i]);
    const int d = __ldg(&deg[i]);

    float wself = __expf(lrelu(__ldg(&asv[i]) + ad_i));
    float denom = wself;
    float acc0 = wself * h[(size_t)i * 64 + lane];
    float acc1 = wself * h[(size_t)i * 64 + 32 + lane];

    for (int k0 = 0; k0 < d; k0 += 32) {
        int kk = k0 + lane;
        int j = 0; float wv = 0.f;
        if (kk < d) {
            j = __ldg(&srcs[base + kk]);
            wv = __expf(lrelu(__ldg(&asv[j]) + ad_i));
        }
        float ws = wv;
        #pragma unroll
        for (int o = 16; o > 0; o >>= 1) ws += __shfl_xor_sync(0xffffffffu, ws, o);
        denom += ws;

        int cnt = min(32, d - k0);
        int k = 0;
        for (; k + 4 <= cnt; k += 4) {
            int j0 = __shfl_sync(0xffffffffu, j, k);
            int j1 = __shfl_sync(0xffffffffu, j, k + 1);
            int j2 = __shfl_sync(0xffffffffu, j, k + 2);
            int j3 = __shfl_sync(0xffffffffu, j, k + 3);
            float w0 = __shfl_sync(0xffffffffu, wv, k);
            float w1 = __shfl_sync(0xffffffffu, wv, k + 1);
            float w2 = __shfl_sync(0xffffffffu, wv, k + 2);
            float w3 = __shfl_sync(0xffffffffu, wv, k + 3);
            float h00 = h[(size_t)j0 * 64 + lane], h01 = h[(size_t)j0 * 64 + 32 + lane];
            float h10 = h[(size_t)j1 * 64 + lane], h11 = h[(size_t)j1 * 64 + 32 + lane];
            float h20 = h[(size_t)j2 * 64 + lane], h21 = h[(size_t)j2 * 64 + 32 + lane];
            float h30 = h[(size_t)j3 * 64 + lane], h31 = h[(size_t)j3 * 64 + 32 + lane];
            acc0 += w0 * h00; acc1 += w0 * h01;
            acc0 += w1 * h10; acc1 += w1 * h11;
            acc0 += w2 * h20; acc1 += w2 * h21;
            acc0 += w3 * h30; acc1 += w3 * h31;
        }
        for (; k < cnt; k++) {
            int jj = __shfl_sync(0xffffffffu, j, k);
            float wk = __shfl_sync(0xffffffffu, wv, k);
            acc0 += wk * h[(size_t)jj * 64 + lane];
            acc1 += wk * h[(size_t)jj * 64 + 32 + lane];
        }
    }
    float inv = 1.0f / (denom + 1e-16f);
    float v0 = acc0 * inv + __ldg(&bias[lane]);
    float v1 = acc1 * inv + __ldg(&bias[32 + lane]);
    out[(size_t)i * 64 + lane]      = DO_ELU ? elu1(v0) : v0;
    out[(size_t)i * 64 + 32 + lane] = DO_ELU ? elu1(v1) : v1;
}

// ============================ fused kernels =================================

// L1: zero degrees + BN accumulators
__global__ void k_zero() {
    int i = blockIdx.x * blockDim.x + threadIdx.x;
    if (i < NNODES) { g_deg1[i] = 0; g_deg2[i] = 0; }
    if (i < 16) { g_bnsum[i] = 0.f; g_bnsumsq[i] = 0.f; }
}

// L2: count1  ||  gemm_dots layer0
__global__ void __launch_bounds__(256) k_count1_gemm0(
    const int* __restrict__ ei1, const float* __restrict__ x1,
    const float* __restrict__ W0, const float* __restrict__ as0,
    const float* __restrict__ ad0) {
    if (blockIdx.x < EB) dev_count(ei1, g_deg1, blockIdx.x);
    else dev_gemm_dots<64, false>(x1, nullptr, W0, as0, ad0,
                                  g_tmpH, g_as, g_ad, blockIdx.x - EB);
}

// L3: scanb1  ||  count2
__global__ void __launch_bounds__(256) k_scanb1_count2(const int* __restrict__ ei2) {
    if (blockIdx.x < NB98) dev_scanb(g_deg1, g_off1, g_bsum1, blockIdx.x);
    else dev_count(ei2, g_deg2, blockIdx.x - NB98);
}

// L4: scanp1  ||  scanb2
__global__ void __launch_bounds__(256) k_scanp1_scanb2() {
    if (blockIdx.x == 0) dev_scanp(g_bsum1);
    else dev_scanb(g_deg2, g_off2, g_bsum2, blockIdx.x - 1);
}

// L5: scana1  ||  scanp2
__global__ void __launch_bounds__(256) k_scana1_scanp2() {
    if (blockIdx.x < NB98) dev_scana(g_off1, g_bsum1, g_cursor1, blockIdx.x);
    else dev_scanp(g_bsum2);
}

// L6: scatter1  ||  scana2
__global__ void __launch_bounds__(256) k_scatter1_scana2(const int* __restrict__ ei1) {
    if (blockIdx.x < EB) dev_scatter(ei1, g_cursor1, g_srcs1, blockIdx.x);
    else dev_scana(g_off2, g_bsum2, g_cursor2, blockIdx.x - EB);
}

// L7: agg0  ||  scatter2
__global__ void __launch_bounds__(256) k_agg0_scatter2(
    const int* __restrict__ ei2, const float* __restrict__ b0) {
    if (blockIdx.x < WARPB)
        dev_agg64<true>(g_tmpH, g_as, g_ad, g_off1, g_deg1, g_srcs1, b0, g_h0, blockIdx.x);
    else
        dev_scatter(ei2, g_cursor2, g_srcs2, blockIdx.x - WARPB);
}

// L8: gemm_dots layer1
__global__ void __launch_bounds__(256) k_gemm1(
    const float* __restrict__ x2, const float* __restrict__ W1,
    const float* __restrict__ as1, const float* __restrict__ ad1) {
    dev_gemm_dots<64, true>(g_h0, x2, W1, as1, ad1, g_tmpH, g_as, g_ad, blockIdx.x);
}

// L9: agg1
__global__ void __launch_bounds__(256) k_agg1(const float* __restrict__ b1) {
    dev_agg64<true>(g_tmpH, g_as, g_ad, g_off2, g_deg2, g_srcs2, b1, g_h1, blockIdx.x);
}

// L10: gemm_dots layer2 (BN=16, BM=256)
__global__ void __launch_bounds__(256) k_gemm2(
    const float* __restrict__ W2, const float* __restrict__ as2,
    const float* __restrict__ ad2) {
    dev_gemm_dots<16, true>(g_h0, g_h1, W2, as2, ad2, g_tmpS, g_as, g_ad, blockIdx.x);
}

// L11: agg layer2 (F=16) with fused BN statistics
__global__ void __launch_bounds__(256) k_agg2_bn(
    const float* __restrict__ b2, float* __restrict__ out) {
    __shared__ float shs[16], shs2[16];
    if (threadIdx.x < 16) { shs[threadIdx.x] = 0.f; shs2[threadIdx.x] = 0.f; }
    __syncthreads();

    const float* __restrict__ h = g_tmpS;
    const int i = blockIdx.x * 8 + (threadIdx.x >> 5);
    const int lane = threadIdx.x & 31;
    const int e = lane >> 4;
    const int f = lane & 15;
    const float ad_i = __ldg(&g_ad[i]);
    const int base = __ldg(&g_off2[i]);
    const int d = __ldg(&g_deg2[i]);

    float wself = __expf(lrelu(__ldg(&g_as[i]) + ad_i));
    float denom = wself;
    float acc = (e == 0) ? wself * h[(size_t)i * 16 + f] : 0.f;

    for (int k0 = 0; k0 < d; k0 += 32) {
        int kk = k0 + lane;
        int j = 0; float wv = 0.f;
        if (kk < d) {
            j = __ldg(&g_srcs2[base + kk]);
            wv = __expf(lrelu(__ldg(&g_as[j]) + ad_i));
        }
        float ws = wv;
        #pragma unroll
        for (int o = 16; o > 0; o >>= 1) ws += __shfl_xor_sync(0xffffffffu, ws, o);
        denom += ws;

        int cnt = min(32, d - k0);
        int k = 0;
        for (; k + 4 <= cnt; k += 4) {
            int ja = __shfl_sync(0xffffffffu, j, k + e);
            int jb = __shfl_sync(0xffffffffu, j, k + 2 + e);
            float wa = __shfl_sync(0xffffffffu, wv, k + e);
            float wb = __shfl_sync(0xffffffffu, wv, k + 2 + e);
            acc += wa * h[(size_t)ja * 16 + f] + wb * h[(size_t)jb * 16 + f];
        }
        for (; k < cnt; k += 2) {
            int km = min(k + e, 31);
            int ja = __shfl_sync(0xffffffffu, j, km);
            float wa = __shfl_sync(0xffffffffu, wv, km);
            if (k + e < cnt) acc += wa * h[(size_t)ja * 16 + f];
        }
    }
    acc += __shfl_xor_sync(0xffffffffu, acc, 16);
    float inv = 1.0f / (denom + 1e-16f);
    if (e == 0) {
        float v = acc * inv + __ldg(&b2[f]);
        out[(size_t)i * 16 + f] = v;
        atomicAdd(&shs[f], v);
        atomicAdd(&shs2[f], v * v);
    }
    __syncthreads();
    if (threadIdx.x < 16) {
        atomicAdd(&g_bnsum[threadIdx.x], shs[threadIdx.x]);
        atomicAdd(&g_bnsumsq[threadIdx.x], shs2[threadIdx.x]);
    }
}

// L12: BN + log_softmax in place
__global__ void __launch_bounds__(256) k_bn_lsm(
    float* __restrict__ out, const float* __restrict__ gamma,
    const float* __restrict__ beta) {
    int i = blockIdx.x * blockDim.x + threadIdx.x;
    if (i >= NNODES) return;
    float y[16];
    float maxv = -1e30f;
    const float invN = 1.0f / (float)NNODES;
    #pragma unroll
    for (int c = 0; c < 16; c++) {
        float mu = g_bnsum[c] * invN;
        float var = g_bnsumsq[c] * invN - mu * mu;
        float v = out[(size_t)i * 16 + c];
        float yy = (v - mu) * rsqrtf(var + BN_EPS_C) * gamma[c] + beta[c];
        y[c] = yy;
        maxv = fmaxf(maxv, yy);
    }
    float s = 0.f;
    #pragma unroll
    for (int c = 0; c < 16; c++) s += expf(y[c] - maxv);
    float lse = maxv + logf(s);
    #pragma unroll
    for (int c = 0; c < 16; c++) out[(size_t)i * 16 + c] = y[c] - lse;
}

// ----------------------------- driver ---------------------------------------
extern "C" void kernel_launch(void* const* d_in, const int* in_sizes, int n_in,
                              void* d_out, int out_size) {
    const float* x1    = (const float*)d_in[0];
    const float* x2    = (const float*)d_in[1];
    const int*   ei1   = (const int*)d_in[2];
    const int*   ei2   = (const int*)d_in[3];
    const float* W0    = (const float*)d_in[4];
    const float* asrc0 = (const float*)d_in[5];
    const float* adst0 = (const float*)d_in[6];
    const float* b0    = (const float*)d_in[7];
    const float* W1    = (const float*)d_in[8];
    const float* asrc1 = (const float*)d_in[9];
    const float* adst1 = (const float*)d_in[10];
    const float* b1    = (const float*)d_in[11];
    const float* W2    = (const float*)d_in[12];
    const float* asrc2 = (const float*)d_in[13];
    const float* adst2 = (const float*)d_in[14];
    const float* b2    = (const float*)d_in[15];
    const float* gamma = (const float*)d_in[16];
    const float* beta  = (const float*)d_in[17];
    float* out = (float*)d_out;

    k_zero<<<GB256, 256>>>();                                         // L1
    k_count1_gemm0<<<EB + GB64, 256>>>(ei1, x1, W0, asrc0, adst0);    // L2
    k_scanb1_count2<<<NB98 + EB, 256>>>(ei2);                         // L3
    k_scanp1_scanb2<<<1 + NB98, 256>>>();                             // L4
    k_scana1_scanp2<<<NB98 + 1, 256>>>();                             // L5
    k_scatter1_scana2<<<EB + NB98, 256>>>(ei1);                       // L6
    k_agg0_scatter2<<<WARPB + EB, 256>>>(ei2, b0);                    // L7
    k_gemm1<<<GB64, 256>>>(x2, W1, asrc1, adst1);                     // L8
    k_agg1<<<WARPB, 256>>>(b1);                                       // L9
    k_gemm2<<<GB256, 256>>>(W2, asrc2, adst2);                        // L10
    k_agg2_bn<<<WARPB, 256>>>(b2, out);                               // L11
    k_bn_lsm<<<GB256, 256>>>(out, gamma, beta);                       // L12
}